// round 6
// baseline (speedup 1.0000x reference)
#include <cuda_runtime.h>
#include <cuda_bf16.h>
#include <math.h>
#include <stdint.h>

// Shapes (fixed): B=2048, D=128, H=512
#define BATCH 2048
#define DDIM  128
#define HDIM  512

// ---------------- device scratch (static; no allocations) ----------------
__device__ float g_ench [BATCH * HDIM];                  // 4 MB
__device__ float g_enc  [BATCH * DDIM];                  // 1 MB
__device__ float g_terms[DDIM * BATCH * DDIM];           // 134 MB (j,b,d)
__device__ __nv_bfloat16 g_w2hi[DDIM * DDIM * HDIM];     // 16.8 MB (j,d,h)
__device__ __nv_bfloat16 g_w2lo[DDIM * DDIM * HDIM];     // 16.8 MB

// ======================= helpers ==========================================
__device__ __forceinline__ uint32_t smem_u32(const void* p) {
    uint32_t a;
    asm("{ .reg .u64 t; cvta.to.shared.u64 t, %1; cvt.u32.u64 %0, t; }"
        : "=r"(a) : "l"(p));
    return a;
}
__device__ __forceinline__ uint32_t pack2(float a, float b) {
    __nv_bfloat162 t = __floats2bfloat162_rn(a, b);
    return *reinterpret_cast<uint32_t*>(&t);
}
// 128B-row swizzle: XOR byte-col bits[6:4] with (row&7)<<4 (bijective per row)
__device__ __forceinline__ uint32_t sw_off(int row, int colb) {
    return (uint32_t)(row * 128 + (colb ^ ((row & 7) << 4)));
}
#define LDSM_X4(r0, r1, r2, r3, addr)                                          \
    asm volatile("ldmatrix.sync.aligned.m8n8.x4.shared.b16 {%0,%1,%2,%3}, [%4];" \
                 : "=r"(r0), "=r"(r1), "=r"(r2), "=r"(r3) : "r"(addr))
#define MMA_BF16(d, a, b)                                                      \
    asm volatile("mma.sync.aligned.m16n8k16.row.col.f32.bf16.bf16.f32 "        \
                 "{%0,%1,%2,%3}, {%4,%5,%6,%7}, {%8,%9}, {%0,%1,%2,%3};"       \
                 : "+f"((d)[0]), "+f"((d)[1]), "+f"((d)[2]), "+f"((d)[3])      \
                 : "r"((a)[0]), "r"((a)[1]), "r"((a)[2]), "r"((a)[3]),         \
                   "r"((b)[0]), "r"((b)[1]))
#define CP_ASYNC16(saddr, gptr)                                                \
    asm volatile("cp.async.cg.shared.global [%0], [%1], 16;"                   \
                 :: "r"(saddr), "l"(gptr) : "memory")
#define CP_COMMIT()       asm volatile("cp.async.commit_group;" ::: "memory")
#define CP_WAIT_GROUP(N)  asm volatile("cp.async.wait_group %0;" :: "n"(N) : "memory")

// ---------------- kernel 1: generic NT GEMM + bias + activation ----------
__global__ void gemm_nt_bias_act(const float* __restrict__ A,
                                 const float* __restrict__ Bw,
                                 const float* __restrict__ bias,
                                 float* __restrict__ C,
                                 int M, int N, int K, int act)
{
    __shared__ __align__(16) float As[32][68];
    __shared__ __align__(16) float Bs[32][68];

    const int t  = threadIdx.x;
    const int m0 = blockIdx.x * 64;
    const int n0 = blockIdx.y * 64;
    const int mg = t >> 4;
    const int ng = t & 15;

    float acc[4][4] = {};

    for (int k0 = 0; k0 < K; k0 += 32) {
        __syncthreads();
#pragma unroll
        for (int i = 0; i < 8; i++) {
            int idx = i * 256 + t;
            int m = idx >> 5, k = idx & 31;
            As[k][m] = A [(size_t)(m0 + m) * K + k0 + k];
            Bs[k][m] = Bw[(size_t)(n0 + m) * K + k0 + k];
        }
        __syncthreads();
#pragma unroll
        for (int k = 0; k < 32; k++) {
            float4 av = *(const float4*)&As[k][mg * 4];
            float4 bv = *(const float4*)&Bs[k][ng * 4];
            float a[4] = {av.x, av.y, av.z, av.w};
            float b[4] = {bv.x, bv.y, bv.z, bv.w};
#pragma unroll
            for (int i = 0; i < 4; i++)
#pragma unroll
                for (int jj = 0; jj < 4; jj++)
                    acc[i][jj] = fmaf(a[i], b[jj], acc[i][jj]);
        }
    }

#pragma unroll
    for (int i = 0; i < 4; i++) {
        int m = m0 + mg * 4 + i;
#pragma unroll
        for (int jj = 0; jj < 4; jj++) {
            int n = n0 + ng * 4 + jj;
            float c = acc[i][jj] + bias[n];
            c = (act == 0) ? fmaxf(c, 0.2f * c) : tanhf(c);
            C[(size_t)m * N + n] = c;
        }
    }
}

// ---------------- kernel 2: split W2s fp32 -> bf16 hi/lo -------------------
__global__ void w2_split_kernel(const float4* __restrict__ w2,
                                uint2* __restrict__ hi, uint2* __restrict__ lo)
{
    int i = blockIdx.x * blockDim.x + threadIdx.x;
    float4 v = w2[i];
    __nv_bfloat16 h0 = __float2bfloat16(v.x), h1 = __float2bfloat16(v.y);
    __nv_bfloat16 h2 = __float2bfloat16(v.z), h3 = __float2bfloat16(v.w);
    float r0 = v.x - __bfloat162float(h0), r1 = v.y - __bfloat162float(h1);
    float r2 = v.z - __bfloat162float(h2), r3 = v.w - __bfloat162float(h3);
    uint2 H, L;
    H.x = pack2(__bfloat162float(h0), __bfloat162float(h1));
    H.y = pack2(__bfloat162float(h2), __bfloat162float(h3));
    L.x = pack2(r0, r1);
    L.y = pack2(r2, r3);
    hi[i] = H;
    lo[i] = L;
}

// ---------------- kernel 3: terms via mma.sync (bf16-split) ----------------
// terms[j][b][d] = sum_h leaky(z*w1+b1) * W2[j][d][h]
// KC=32, hi|lo packed in one 128B row (cols 0-63 hi, 64-127 lo).
// Triple-buffered A and B stages -> ONE __syncthreads per chunk.
#define KC 32
#define NCHUNK (HDIM / KC)              // 16
#define SM_Z     0
#define SM_W1    512
#define SM_B1    2560
#define SM_TILE0 4608
#define STG_SZ   16384                  // 128 rows x 128 B (hi|lo combined)
#define S_A(s)   (SM_TILE0 + (s) * STG_SZ)
#define S_B(s)   (SM_TILE0 + (3 + (s)) * STG_SZ)
#define SMEM_TOTAL (SM_TILE0 + 6 * STG_SZ)   // 102912 B -> 2 CTAs/SM

__global__ __launch_bounds__(256, 2)
void terms_mma_kernel(const float* __restrict__ encoded,
                      const float* __restrict__ W1s,
                      const float* __restrict__ b1s,
                      const __nv_bfloat16* __restrict__ w2hi,
                      const __nv_bfloat16* __restrict__ w2lo,
                      float* __restrict__ terms)
{
    extern __shared__ __align__(128) char smem[];
    const uint32_t sbase = smem_u32(smem);
    const int t   = threadIdx.x;
    const int l   = t & 31;
    const int wid = t >> 5;
    const int j   = blockIdx.y;
    const int b0  = blockIdx.x * 128;

    float* z_s  = (float*)(smem + SM_Z);
    float* w1_s = (float*)(smem + SM_W1);
    float* b1_s = (float*)(smem + SM_B1);

    w1_s[t]       = W1s[(size_t)j * HDIM + t];
    w1_s[t + 256] = W1s[(size_t)j * HDIM + t + 256];
    b1_s[t]       = b1s[(size_t)j * HDIM + t];
    b1_s[t + 256] = b1s[(size_t)j * HDIM + t + 256];
    if (t < 128) z_s[t] = encoded[(size_t)(b0 + t) * DDIM + j];
    __syncthreads();

    // ---- per-thread constants ----
    const int m0 = (wid & 1) * 64;              // warp m origin (b)
    const int n0 = (wid >> 1) * 32;             // warp n origin (d)
    const int ar  = ((l >> 3) & 1) * 8 + (l & 7);
    const int ac2 = (l >> 4) * 16;
    const uint32_t swA = (uint32_t)((ar & 7) << 4);
    const int br  = (l >> 4) * 8 + (l & 7);
    const int bc2 = ((l >> 3) & 1) * 16;
    const uint32_t swB = (uint32_t)((br & 7) << 4);
    // A producer: thread -> (b row, k group of 16)
    const int pb  = t & 127;
    const int pk  = (t >> 7) * 16;              // k base within chunk (0 or 16)
    const float z = z_s[pb];
    // B producer: thread -> (d row pair, 16B segment)
    const int bseg = t & 3;                     // 16B segment in 64B hi region
    const int bd0  = t >> 2;                    // 0..63

    float acc[4][4][4] = {};

    auto loadB = [&](int c, int s) {
        const int hc = c * KC;
#pragma unroll
        for (int p = 0; p < 2; ++p) {
            const int d = p * 64 + bd0;
            const size_t goff = ((size_t)j * DDIM + d) * HDIM + hc + bseg * 8;
            CP_ASYNC16(sbase + S_B(s) + sw_off(d, bseg * 16),      w2hi + goff);
            CP_ASYNC16(sbase + S_B(s) + sw_off(d, 64 + bseg * 16), w2lo + goff);
        }
    };
    auto storeA = [&](int c, int s) {
        const int hc = c * KC;
#pragma unroll
        for (int i = 0; i < 2; ++i) {
            const int h = pk + i * 8;
            float v[8], r[8];
#pragma unroll
            for (int q = 0; q < 8; ++q) {
                float u = fmaf(z, w1_s[hc + h + q], b1_s[hc + h + q]);
                u = fmaxf(u, 0.2f * u);
                __nv_bfloat16 hb = __float2bfloat16(u);
                float hf = __bfloat162float(hb);
                v[q] = hf;
                r[q] = u - hf;
            }
            uint4 H, L;
            H.x = pack2(v[0], v[1]); H.y = pack2(v[2], v[3]);
            H.z = pack2(v[4], v[5]); H.w = pack2(v[6], v[7]);
            L.x = pack2(r[0], r[1]); L.y = pack2(r[2], r[3]);
            L.z = pack2(r[4], r[5]); L.w = pack2(r[6], r[7]);
            *(uint4*)(smem + S_A(s) + sw_off(pb, h * 2))      = H;
            *(uint4*)(smem + S_A(s) + sw_off(pb, 64 + h * 2)) = L;
        }
    };

    auto hmma = [&](int s) {
        const uint32_t aB = sbase + S_A(s);
        const uint32_t bB = sbase + S_B(s);
#pragma unroll
        for (int ks = 0; ks < KC / 16; ++ks) {
            const int kb = ks * 32;
            uint32_t bh[4][2], bl[4][2];
#pragma unroll
            for (int np = 0; np < 2; ++np) {
                const uint32_t ro = (uint32_t)((n0 + np * 16 + br) * 128);
                const uint32_t ch = (uint32_t)(kb + bc2) ^ swB;
                const uint32_t cl = (uint32_t)(64 + kb + bc2) ^ swB;
                LDSM_X4(bh[np*2][0], bh[np*2][1], bh[np*2+1][0], bh[np*2+1][1],
                        bB + ro + ch);
                LDSM_X4(bl[np*2][0], bl[np*2][1], bl[np*2+1][0], bl[np*2+1][1],
                        bB + ro + cl);
            }
#pragma unroll
            for (int mt = 0; mt < 4; ++mt) {
                const uint32_t ro = (uint32_t)((m0 + mt * 16 + ar) * 128);
                uint32_t ah[4], al[4];
                LDSM_X4(ah[0], ah[1], ah[2], ah[3],
                        aB + ro + ((uint32_t)(kb + ac2) ^ swA));
                LDSM_X4(al[0], al[1], al[2], al[3],
                        aB + ro + ((uint32_t)(64 + kb + ac2) ^ swA));
#pragma unroll
                for (int nt = 0; nt < 4; ++nt) {
                    MMA_BF16(acc[mt][nt], ah, bh[nt]);
                    MMA_BF16(acc[mt][nt], ah, bl[nt]);
                    MMA_BF16(acc[mt][nt], al, bh[nt]);
                }
            }
        }
    };

    // ---- pipeline: triple-buffered stages, one sync per chunk ----
    loadB(0, 0);
    CP_COMMIT();
    storeA(0, 0);

    int s_cur = 0, s_nxt = 1;
    for (int c = 0; c < NCHUNK; ++c) {
        if (c + 1 < NCHUNK) {
            loadB(c + 1, s_nxt);
            CP_COMMIT();
            storeA(c + 1, s_nxt);
            CP_WAIT_GROUP(1);       // B(c) complete, B(c+1) in flight
        } else {
            CP_WAIT_GROUP(0);
        }
        __syncthreads();            // A(c)/B(c) visible; frees stage c-2
        hmma(s_cur);
        s_cur = s_nxt;
        s_nxt = (s_nxt == 2) ? 0 : s_nxt + 1;
    }

    // ---- epilogue: direct fp32 stores ----
    const int t4 = l >> 2, tn = (l & 3) * 2;
#pragma unroll
    for (int mt = 0; mt < 4; ++mt) {
        const int row0 = b0 + m0 + mt * 16 + t4;
        float* p0 = terms + ((size_t)j * BATCH + row0) * DDIM;
        float* p1 = terms + ((size_t)j * BATCH + row0 + 8) * DDIM;
#pragma unroll
        for (int nt = 0; nt < 4; ++nt) {
            const int col = n0 + nt * 8 + tn;
            *(float2*)&p0[col] = make_float2(acc[mt][nt][0], acc[mt][nt][1]);
            *(float2*)&p1[col] = make_float2(acc[mt][nt][2], acc[mt][nt][3]);
        }
    }
}

// ---------------- kernel 4: cumsum over j + bias + tanh --------------------
__global__ __launch_bounds__(256)
void cumsum_tanh(const float* __restrict__ terms,
                 const float* __restrict__ b2s,
                 float* __restrict__ out)
{
    const int g  = blockIdx.x * 256 + threadIdx.x;
    const int dq = g & 31;
    const size_t jstride = (size_t)BATCH * DDIM / 4;

    const float4* tp = (const float4*)terms + g;
    float4*       op = (float4*)out + g;
    const float4* bp = (const float4*)b2s + dq;

    float4 acc = make_float4(0.f, 0.f, 0.f, 0.f);
#pragma unroll 4
    for (int j = 0; j < DDIM; j++) {
        float4 tv = tp[(size_t)j * jstride];
        float4 bv = bp[(size_t)j * (DDIM / 4)];
        acc.x += tv.x + bv.x;
        acc.y += tv.y + bv.y;
        acc.z += tv.z + bv.z;
        acc.w += tv.w + bv.w;
        float4 o = make_float4(tanhf(acc.x), tanhf(acc.y),
                               tanhf(acc.z), tanhf(acc.w));
        op[(size_t)j * jstride] = o;
    }
}

// ---------------- launch ---------------------------------------------------
extern "C" void kernel_launch(void* const* d_in, const int* in_sizes, int n_in,
                              void* d_out, int out_size)
{
    const float* x   = (const float*)d_in[0];
    const float* We1 = (const float*)d_in[1];
    const float* be1 = (const float*)d_in[2];
    const float* We2 = (const float*)d_in[3];
    const float* be2 = (const float*)d_in[4];
    const float* W1s = (const float*)d_in[5];
    const float* b1s = (const float*)d_in[6];
    const float* W2s = (const float*)d_in[7];
    const float* b2s = (const float*)d_in[8];
    float* out = (float*)d_out;

    float *ench, *enc, *terms;
    __nv_bfloat16 *w2hi, *w2lo;
    cudaGetSymbolAddress((void**)&ench,  g_ench);
    cudaGetSymbolAddress((void**)&enc,   g_enc);
    cudaGetSymbolAddress((void**)&terms, g_terms);
    cudaGetSymbolAddress((void**)&w2hi,  g_w2hi);
    cudaGetSymbolAddress((void**)&w2lo,  g_w2lo);

    cudaFuncSetAttribute(terms_mma_kernel,
                         cudaFuncAttributeMaxDynamicSharedMemorySize, SMEM_TOTAL);

    w2_split_kernel<<<(DDIM * DDIM * HDIM / 4) / 256, 256>>>(
        (const float4*)W2s, (uint2*)w2hi, (uint2*)w2lo);

    gemm_nt_bias_act<<<dim3(BATCH / 64, HDIM / 64), 256>>>(
        x, We1, be1, ench, BATCH, HDIM, DDIM, 0);
    gemm_nt_bias_act<<<dim3(BATCH / 64, DDIM / 64), 256>>>(
        ench, We2, be2, enc, BATCH, DDIM, HDIM, 1);

    terms_mma_kernel<<<dim3(BATCH / 128, DDIM), 256, SMEM_TOTAL>>>(
        enc, W1s, b1s, w2hi, w2lo, terms);

    cumsum_tanh<<<(BATCH * DDIM / 4) / 256, 256>>>(terms, b2s, out);
}

// round 7
// speedup vs baseline: 1.0129x; 1.0129x over previous
#include <cuda_runtime.h>
#include <cuda_bf16.h>
#include <math.h>
#include <stdint.h>

// Shapes (fixed): B=2048, D=128, H=512
#define BATCH 2048
#define DDIM  128
#define HDIM  512

// ---------------- device scratch (static; no allocations) ----------------
__device__ float g_ench [BATCH * HDIM];                  // 4 MB
__device__ float g_enc  [BATCH * DDIM];                  // 1 MB
__device__ float g_terms[DDIM * BATCH * DDIM];           // 134 MB (j,b,d)
__device__ __nv_bfloat16 g_w2hi[DDIM * DDIM * HDIM];     // 16.8 MB (j,d,h)
__device__ __nv_bfloat16 g_w2lo[DDIM * DDIM * HDIM];     // 16.8 MB

// ======================= helpers ==========================================
__device__ __forceinline__ uint32_t smem_u32(const void* p) {
    uint32_t a;
    asm("{ .reg .u64 t; cvta.to.shared.u64 t, %1; cvt.u32.u64 %0, t; }"
        : "=r"(a) : "l"(p));
    return a;
}
__device__ __forceinline__ uint32_t pack2(float a, float b) {
    __nv_bfloat162 t = __floats2bfloat162_rn(a, b);
    return *reinterpret_cast<uint32_t*>(&t);
}
// 128B-row swizzle: XOR byte-col bits[6:4] with (row&7)<<4 (bijective per row)
__device__ __forceinline__ uint32_t sw_off(int row, int colb) {
    return (uint32_t)(row * 128 + (colb ^ ((row & 7) << 4)));
}
#define LDSM_X4(r0, r1, r2, r3, addr)                                          \
    asm volatile("ldmatrix.sync.aligned.m8n8.x4.shared.b16 {%0,%1,%2,%3}, [%4];" \
                 : "=r"(r0), "=r"(r1), "=r"(r2), "=r"(r3) : "r"(addr))
#define MMA_BF16(d, a, b)                                                      \
    asm volatile("mma.sync.aligned.m16n8k16.row.col.f32.bf16.bf16.f32 "        \
                 "{%0,%1,%2,%3}, {%4,%5,%6,%7}, {%8,%9}, {%0,%1,%2,%3};"       \
                 : "+f"((d)[0]), "+f"((d)[1]), "+f"((d)[2]), "+f"((d)[3])      \
                 : "r"((a)[0]), "r"((a)[1]), "r"((a)[2]), "r"((a)[3]),         \
                   "r"((b)[0]), "r"((b)[1]))
#define CP_ASYNC16(saddr, gptr)                                                \
    asm volatile("cp.async.cg.shared.global [%0], [%1], 16;"                   \
                 :: "r"(saddr), "l"(gptr) : "memory")
#define CP_COMMIT()  asm volatile("cp.async.commit_group;" ::: "memory")
#define CP_WAIT0()   asm volatile("cp.async.wait_group 0;" ::: "memory")

// ---------------- kernel 1: generic NT GEMM + bias + activation ----------
__global__ void gemm_nt_bias_act(const float* __restrict__ A,
                                 const float* __restrict__ Bw,
                                 const float* __restrict__ bias,
                                 float* __restrict__ C,
                                 int M, int N, int K, int act)
{
    __shared__ __align__(16) float As[32][68];
    __shared__ __align__(16) float Bs[32][68];

    const int t  = threadIdx.x;
    const int m0 = blockIdx.x * 64;
    const int n0 = blockIdx.y * 64;
    const int mg = t >> 4;
    const int ng = t & 15;

    float acc[4][4] = {};

    for (int k0 = 0; k0 < K; k0 += 32) {
        __syncthreads();
#pragma unroll
        for (int i = 0; i < 8; i++) {
            int idx = i * 256 + t;
            int m = idx >> 5, k = idx & 31;
            As[k][m] = A [(size_t)(m0 + m) * K + k0 + k];
            Bs[k][m] = Bw[(size_t)(n0 + m) * K + k0 + k];
        }
        __syncthreads();
#pragma unroll
        for (int k = 0; k < 32; k++) {
            float4 av = *(const float4*)&As[k][mg * 4];
            float4 bv = *(const float4*)&Bs[k][ng * 4];
            float a[4] = {av.x, av.y, av.z, av.w};
            float b[4] = {bv.x, bv.y, bv.z, bv.w};
#pragma unroll
            for (int i = 0; i < 4; i++)
#pragma unroll
                for (int jj = 0; jj < 4; jj++)
                    acc[i][jj] = fmaf(a[i], b[jj], acc[i][jj]);
        }
    }

#pragma unroll
    for (int i = 0; i < 4; i++) {
        int m = m0 + mg * 4 + i;
#pragma unroll
        for (int jj = 0; jj < 4; jj++) {
            int n = n0 + ng * 4 + jj;
            float c = acc[i][jj] + bias[n];
            c = (act == 0) ? fmaxf(c, 0.2f * c) : tanhf(c);
            C[(size_t)m * N + n] = c;
        }
    }
}

// ---------------- kernel 2: split W2s fp32 -> bf16 hi/lo -------------------
__global__ void w2_split_kernel(const float4* __restrict__ w2,
                                uint2* __restrict__ hi, uint2* __restrict__ lo)
{
    int i = blockIdx.x * blockDim.x + threadIdx.x;
    float4 v = w2[i];
    __nv_bfloat16 h0 = __float2bfloat16(v.x), h1 = __float2bfloat16(v.y);
    __nv_bfloat16 h2 = __float2bfloat16(v.z), h3 = __float2bfloat16(v.w);
    float r0 = v.x - __bfloat162float(h0), r1 = v.y - __bfloat162float(h1);
    float r2 = v.z - __bfloat162float(h2), r3 = v.w - __bfloat162float(h3);
    uint2 H, L;
    H.x = pack2(__bfloat162float(h0), __bfloat162float(h1));
    H.y = pack2(__bfloat162float(h2), __bfloat162float(h3));
    L.x = pack2(r0, r1);
    L.y = pack2(r2, r3);
    hi[i] = H;
    lo[i] = L;
}

// ---------------- kernel 3: terms via mma.sync (bf16-split) ----------------
// terms[j][b][d] = sum_h leaky(z*w1+b1) * W2[j][d][h]
// CTA tile: M=64 (b) x N=128 (d), K=512 in 8 chunks of 64. Grid 4096.
// 8 warps in 2(m) x 4(n), warp tile 32x32. Single A buffer + double B buffer.
#define KC 64
#define SM_Z     0
#define SM_W1    512
#define SM_B1    2560
#define SM_TILE0 4608
#define AMAT_SZ  8192                     // 64 x 64 bf16
#define BMAT_SZ  16384                    // 128 x 64 bf16
#define S_AHI    (SM_TILE0)
#define S_ALO    (SM_TILE0 + AMAT_SZ)
#define S_B0     (SM_TILE0 + 2 * AMAT_SZ)
#define S_BHI(b) (S_B0 + (b) * 2 * BMAT_SZ)
#define S_BLO(b) (S_B0 + (b) * 2 * BMAT_SZ + BMAT_SZ)
#define SMEM_TOTAL (S_B0 + 4 * BMAT_SZ)   // 86528 B -> 2 CTAs/SM

__global__ __launch_bounds__(256, 2)
void terms_mma_kernel(const float* __restrict__ encoded,
                      const float* __restrict__ W1s,
                      const float* __restrict__ b1s,
                      const __nv_bfloat16* __restrict__ w2hi,
                      const __nv_bfloat16* __restrict__ w2lo,
                      float* __restrict__ terms)
{
    extern __shared__ __align__(128) char smem[];
    const uint32_t sbase = smem_u32(smem);
    const int t   = threadIdx.x;
    const int l   = t & 31;
    const int wid = t >> 5;
    const int j   = blockIdx.y;
    const int b0  = blockIdx.x * 64;

    float* z_s  = (float*)(smem + SM_Z);
    float* w1_s = (float*)(smem + SM_W1);
    float* b1_s = (float*)(smem + SM_B1);

    w1_s[t]       = W1s[(size_t)j * HDIM + t];
    w1_s[t + 256] = W1s[(size_t)j * HDIM + t + 256];
    b1_s[t]       = b1s[(size_t)j * HDIM + t];
    b1_s[t + 256] = b1s[(size_t)j * HDIM + t + 256];
    if (t < 64) z_s[t] = encoded[(size_t)(b0 + t) * DDIM + j];
    __syncthreads();

    // ---- per-thread constants ----
    const int m0 = (wid & 1) * 32;              // warp m origin (b)
    const int n0 = (wid >> 1) * 32;             // warp n origin (d)
    const int ar  = ((l >> 3) & 1) * 8 + (l & 7);
    const int ac2 = (l >> 4) * 16;
    const uint32_t swA = (uint32_t)((ar & 7) << 4);
    const int br  = (l >> 4) * 8 + (l & 7);
    const int bc2 = ((l >> 3) & 1) * 16;
    const uint32_t swB = (uint32_t)((br & 7) << 4);
    // A producer: thread -> (b row 0..63, k group of 16)
    const int pb  = t & 63;
    const int pk  = (t >> 6) * 16;              // 0,16,32,48
    const float z = z_s[pb];
    // B producer: thread -> (d rows, 16B segment)
    const int bseg = t & 7;
    const int bd0  = t >> 3;

    float acc[2][4][4] = {};

    auto loadB = [&](int c, int buf) {
        const int hc = c * KC;
#pragma unroll
        for (int p = 0; p < 4; ++p) {
            const int d = p * 32 + bd0;
            const size_t goff = ((size_t)j * DDIM + d) * HDIM + hc + bseg * 8;
            const uint32_t so = sw_off(d, bseg * 16);
            CP_ASYNC16(sbase + S_BHI(buf) + so, w2hi + goff);
            CP_ASYNC16(sbase + S_BLO(buf) + so, w2lo + goff);
        }
    };
    auto storeA = [&](int c) {
        const int hc = c * KC;
#pragma unroll
        for (int i = 0; i < 2; ++i) {
            const int h = pk + i * 8;
            float v[8], r[8];
#pragma unroll
            for (int q = 0; q < 8; ++q) {
                float u = fmaf(z, w1_s[hc + h + q], b1_s[hc + h + q]);
                u = fmaxf(u, 0.2f * u);
                __nv_bfloat16 hb = __float2bfloat16(u);
                float hf = __bfloat162float(hb);
                v[q] = hf;
                r[q] = u - hf;
            }
            uint4 H, L;
            H.x = pack2(v[0], v[1]); H.y = pack2(v[2], v[3]);
            H.z = pack2(v[4], v[5]); H.w = pack2(v[6], v[7]);
            L.x = pack2(r[0], r[1]); L.y = pack2(r[2], r[3]);
            L.z = pack2(r[4], r[5]); L.w = pack2(r[6], r[7]);
            const uint32_t so = sw_off(pb, h * 2);
            *(uint4*)(smem + S_AHI + so) = H;
            *(uint4*)(smem + S_ALO + so) = L;
        }
    };

    auto hmma = [&](int buf) {
        const uint32_t aHi = sbase + S_AHI, aLo = sbase + S_ALO;
        const uint32_t bHi = sbase + S_BHI(buf), bLo = sbase + S_BLO(buf);
#pragma unroll
        for (int ks = 0; ks < KC / 16; ++ks) {
            const int kb = ks * 32;
            uint32_t bh[4][2], bl[4][2];
#pragma unroll
            for (int np = 0; np < 2; ++np) {
                const uint32_t ro = (uint32_t)((n0 + np * 16 + br) * 128);
                const uint32_t co = (uint32_t)(kb + bc2) ^ swB;
                LDSM_X4(bh[np*2][0], bh[np*2][1], bh[np*2+1][0], bh[np*2+1][1],
                        bHi + ro + co);
                LDSM_X4(bl[np*2][0], bl[np*2][1], bl[np*2+1][0], bl[np*2+1][1],
                        bLo + ro + co);
            }
#pragma unroll
            for (int mt = 0; mt < 2; ++mt) {
                const uint32_t ro = (uint32_t)((m0 + mt * 16 + ar) * 128);
                const uint32_t co = (uint32_t)(kb + ac2) ^ swA;
                uint32_t ah[4], al[4];
                LDSM_X4(ah[0], ah[1], ah[2], ah[3], aHi + ro + co);
                LDSM_X4(al[0], al[1], al[2], al[3], aLo + ro + co);
#pragma unroll
                for (int nt = 0; nt < 4; ++nt) {
                    MMA_BF16(acc[mt][nt], ah, bh[nt]);
                    MMA_BF16(acc[mt][nt], ah, bl[nt]);
                    MMA_BF16(acc[mt][nt], al, bh[nt]);
                }
            }
        }
    };

    // ---- pipeline: single A buffer, double B buffer (R5 structure) ----
    loadB(0, 0);
    CP_COMMIT();
    storeA(0);
    CP_WAIT0();
    __syncthreads();

    for (int c = 0; c < HDIM / KC; ++c) {
        const int buf = c & 1;
        if (c < HDIM / KC - 1) { loadB(c + 1, buf ^ 1); CP_COMMIT(); }
        hmma(buf);
        if (c < HDIM / KC - 1) {
            __syncthreads();        // all warps finished reading A chunk c
            storeA(c + 1);          // overwrite single A buffer
            CP_WAIT0();
            __syncthreads();        // A(c+1) + B(c+1) visible
        }
    }

    // ---- epilogue: direct fp32 stores ----
    const int t4 = l >> 2, tn = (l & 3) * 2;
#pragma unroll
    for (int mt = 0; mt < 2; ++mt) {
        const int row0 = b0 + m0 + mt * 16 + t4;
        float* p0 = terms + ((size_t)j * BATCH + row0) * DDIM;
        float* p1 = terms + ((size_t)j * BATCH + row0 + 8) * DDIM;
#pragma unroll
        for (int nt = 0; nt < 4; ++nt) {
            const int col = n0 + nt * 8 + tn;
            *(float2*)&p0[col] = make_float2(acc[mt][nt][0], acc[mt][nt][1]);
            *(float2*)&p1[col] = make_float2(acc[mt][nt][2], acc[mt][nt][3]);
        }
    }
}

// ---------------- kernel 4: cumsum over j + bias + tanh --------------------
__global__ __launch_bounds__(256)
void cumsum_tanh(const float* __restrict__ terms,
                 const float* __restrict__ b2s,
                 float* __restrict__ out)
{
    const int g  = blockIdx.x * 256 + threadIdx.x;
    const int dq = g & 31;
    const size_t jstride = (size_t)BATCH * DDIM / 4;

    const float4* tp = (const float4*)terms + g;
    float4*       op = (float4*)out + g;
    const float4* bp = (const float4*)b2s + dq;

    float4 acc = make_float4(0.f, 0.f, 0.f, 0.f);
#pragma unroll 4
    for (int j = 0; j < DDIM; j++) {
        float4 tv = tp[(size_t)j * jstride];
        float4 bv = bp[(size_t)j * (DDIM / 4)];
        acc.x += tv.x + bv.x;
        acc.y += tv.y + bv.y;
        acc.z += tv.z + bv.z;
        acc.w += tv.w + bv.w;
        float4 o = make_float4(tanhf(acc.x), tanhf(acc.y),
                               tanhf(acc.z), tanhf(acc.w));
        op[(size_t)j * jstride] = o;
    }
}

// ---------------- launch ---------------------------------------------------
extern "C" void kernel_launch(void* const* d_in, const int* in_sizes, int n_in,
                              void* d_out, int out_size)
{
    const float* x   = (const float*)d_in[0];
    const float* We1 = (const float*)d_in[1];
    const float* be1 = (const float*)d_in[2];
    const float* We2 = (const float*)d_in[3];
    const float* be2 = (const float*)d_in[4];
    const float* W1s = (const float*)d_in[5];
    const float* b1s = (const float*)d_in[6];
    const float* W2s = (const float*)d_in[7];
    const float* b2s = (const float*)d_in[8];
    float* out = (float*)d_out;

    float *ench, *enc, *terms;
    __nv_bfloat16 *w2hi, *w2lo;
    cudaGetSymbolAddress((void**)&ench,  g_ench);
    cudaGetSymbolAddress((void**)&enc,   g_enc);
    cudaGetSymbolAddress((void**)&terms, g_terms);
    cudaGetSymbolAddress((void**)&w2hi,  g_w2hi);
    cudaGetSymbolAddress((void**)&w2lo,  g_w2lo);

    cudaFuncSetAttribute(terms_mma_kernel,
                         cudaFuncAttributeMaxDynamicSharedMemorySize, SMEM_TOTAL);

    w2_split_kernel<<<(DDIM * DDIM * HDIM / 4) / 256, 256>>>(
        (const float4*)W2s, (uint2*)w2hi, (uint2*)w2lo);

    gemm_nt_bias_act<<<dim3(BATCH / 64, HDIM / 64), 256>>>(
        x, We1, be1, ench, BATCH, HDIM, DDIM, 0);
    gemm_nt_bias_act<<<dim3(BATCH / 64, DDIM / 64), 256>>>(
        ench, We2, be2, enc, BATCH, DDIM, HDIM, 1);

    terms_mma_kernel<<<dim3(BATCH / 64, DDIM), 256, SMEM_TOTAL>>>(
        enc, W1s, b1s, w2hi, w2lo, terms);

    cumsum_tanh<<<(BATCH * DDIM / 4) / 256, 256>>>(terms, b2s, out);
}

// round 8
// speedup vs baseline: 1.0138x; 1.0009x over previous
#include <cuda_runtime.h>
#include <cuda_bf16.h>
#include <math.h>
#include <stdint.h>

// Shapes (fixed): B=2048, D=128, H=512
#define BATCH 2048
#define DDIM  128
#define HDIM  512

// ---------------- device scratch (static; no allocations) ----------------
__device__ float g_ench [BATCH * HDIM];                  // 4 MB
__device__ float g_enc  [BATCH * DDIM];                  // 1 MB
__device__ float g_terms[DDIM * BATCH * DDIM];           // 134 MB (j,b,d)
__device__ __nv_bfloat16 g_w2hi[DDIM * DDIM * HDIM];     // 16.8 MB (j,d,h)
__device__ __nv_bfloat16 g_w2lo[DDIM * DDIM * HDIM];     // 16.8 MB

// ======================= helpers ==========================================
__device__ __forceinline__ uint32_t smem_u32(const void* p) {
    uint32_t a;
    asm("{ .reg .u64 t; cvta.to.shared.u64 t, %1; cvt.u32.u64 %0, t; }"
        : "=r"(a) : "l"(p));
    return a;
}
__device__ __forceinline__ uint32_t pack2(float a, float b) {
    __nv_bfloat162 t = __floats2bfloat162_rn(a, b);
    return *reinterpret_cast<uint32_t*>(&t);
}
// 128B-row swizzle: XOR byte-col bits[6:4] with (row&7)<<4 (bijective per row)
__device__ __forceinline__ uint32_t sw_off(int row, int colb) {
    return (uint32_t)(row * 128 + (colb ^ ((row & 7) << 4)));
}
#define LDSM_X4(r0, r1, r2, r3, addr)                                          \
    asm volatile("ldmatrix.sync.aligned.m8n8.x4.shared.b16 {%0,%1,%2,%3}, [%4];" \
                 : "=r"(r0), "=r"(r1), "=r"(r2), "=r"(r3) : "r"(addr))
#define MMA_BF16(d, a, b)                                                      \
    asm volatile("mma.sync.aligned.m16n8k16.row.col.f32.bf16.bf16.f32 "        \
                 "{%0,%1,%2,%3}, {%4,%5,%6,%7}, {%8,%9}, {%0,%1,%2,%3};"       \
                 : "+f"((d)[0]), "+f"((d)[1]), "+f"((d)[2]), "+f"((d)[3])      \
                 : "r"((a)[0]), "r"((a)[1]), "r"((a)[2]), "r"((a)[3]),         \
                   "r"((b)[0]), "r"((b)[1]))
#define CP_ASYNC16(saddr, gptr)                                                \
    asm volatile("cp.async.cg.shared.global [%0], [%1], 16;"                   \
                 :: "r"(saddr), "l"(gptr) : "memory")
#define CP_COMMIT()  asm volatile("cp.async.commit_group;" ::: "memory")
#define CP_WAIT0()   asm volatile("cp.async.wait_group 0;" ::: "memory")

// ---------------- kernel 1: generic NT GEMM + bias + activation ----------
__global__ void gemm_nt_bias_act(const float* __restrict__ A,
                                 const float* __restrict__ Bw,
                                 const float* __restrict__ bias,
                                 float* __restrict__ C,
                                 int M, int N, int K, int act)
{
    __shared__ __align__(16) float As[32][68];
    __shared__ __align__(16) float Bs[32][68];

    const int t  = threadIdx.x;
    const int m0 = blockIdx.x * 64;
    const int n0 = blockIdx.y * 64;
    const int mg = t >> 4;
    const int ng = t & 15;

    float acc[4][4] = {};

    for (int k0 = 0; k0 < K; k0 += 32) {
        __syncthreads();
#pragma unroll
        for (int i = 0; i < 8; i++) {
            int idx = i * 256 + t;
            int m = idx >> 5, k = idx & 31;
            As[k][m] = A [(size_t)(m0 + m) * K + k0 + k];
            Bs[k][m] = Bw[(size_t)(n0 + m) * K + k0 + k];
        }
        __syncthreads();
#pragma unroll
        for (int k = 0; k < 32; k++) {
            float4 av = *(const float4*)&As[k][mg * 4];
            float4 bv = *(const float4*)&Bs[k][ng * 4];
            float a[4] = {av.x, av.y, av.z, av.w};
            float b[4] = {bv.x, bv.y, bv.z, bv.w};
#pragma unroll
            for (int i = 0; i < 4; i++)
#pragma unroll
                for (int jj = 0; jj < 4; jj++)
                    acc[i][jj] = fmaf(a[i], b[jj], acc[i][jj]);
        }
    }

#pragma unroll
    for (int i = 0; i < 4; i++) {
        int m = m0 + mg * 4 + i;
#pragma unroll
        for (int jj = 0; jj < 4; jj++) {
            int n = n0 + ng * 4 + jj;
            float c = acc[i][jj] + bias[n];
            c = (act == 0) ? fmaxf(c, 0.2f * c) : tanhf(c);
            C[(size_t)m * N + n] = c;
        }
    }
}

// ---------------- kernel 2: split W2s fp32 -> bf16 hi/lo -------------------
__global__ void w2_split_kernel(const float4* __restrict__ w2,
                                uint2* __restrict__ hi, uint2* __restrict__ lo)
{
    int i = blockIdx.x * blockDim.x + threadIdx.x;
    float4 v = w2[i];
    __nv_bfloat16 h0 = __float2bfloat16(v.x), h1 = __float2bfloat16(v.y);
    __nv_bfloat16 h2 = __float2bfloat16(v.z), h3 = __float2bfloat16(v.w);
    float r0 = v.x - __bfloat162float(h0), r1 = v.y - __bfloat162float(h1);
    float r2 = v.z - __bfloat162float(h2), r3 = v.w - __bfloat162float(h3);
    uint2 H, L;
    H.x = pack2(__bfloat162float(h0), __bfloat162float(h1));
    H.y = pack2(__bfloat162float(h2), __bfloat162float(h3));
    L.x = pack2(r0, r1);
    L.y = pack2(r2, r3);
    hi[i] = H;
    lo[i] = L;
}

// ---------------- kernel 3: terms via mma.sync (bf16-split) ----------------
// terms[j][b][d] = sum_h leaky(z*w1+b1) * W2[j][d][h]
// CTA tile: M=64 (b) x N=128 (d), K=512 in 8 chunks of 64. Grid 4096.
// 8 warps in 2(m) x 4(n), warp tile 32x32.
// DOUBLE A + DOUBLE B buffers -> one __syncthreads per chunk, free warp drift.
#define KC 64
#define SM_Z     0
#define SM_W1    512
#define SM_B1    2560
#define SM_TILE0 4608
#define AMAT_SZ  8192                     // 64 x 64 bf16
#define BMAT_SZ  16384                    // 128 x 64 bf16
#define S_AHI(b) (SM_TILE0 + (b) * 2 * AMAT_SZ)
#define S_ALO(b) (SM_TILE0 + (b) * 2 * AMAT_SZ + AMAT_SZ)
#define S_B0     (SM_TILE0 + 4 * AMAT_SZ)
#define S_BHI(b) (S_B0 + (b) * 2 * BMAT_SZ)
#define S_BLO(b) (S_B0 + (b) * 2 * BMAT_SZ + BMAT_SZ)
#define SMEM_TOTAL (S_B0 + 4 * BMAT_SZ)   // 102912 B -> 2 CTAs/SM

__global__ __launch_bounds__(256, 2)
void terms_mma_kernel(const float* __restrict__ encoded,
                      const float* __restrict__ W1s,
                      const float* __restrict__ b1s,
                      const __nv_bfloat16* __restrict__ w2hi,
                      const __nv_bfloat16* __restrict__ w2lo,
                      float* __restrict__ terms)
{
    extern __shared__ __align__(128) char smem[];
    const uint32_t sbase = smem_u32(smem);
    const int t   = threadIdx.x;
    const int l   = t & 31;
    const int wid = t >> 5;
    const int j   = blockIdx.y;
    const int b0  = blockIdx.x * 64;

    float* z_s  = (float*)(smem + SM_Z);
    float* w1_s = (float*)(smem + SM_W1);
    float* b1_s = (float*)(smem + SM_B1);

    w1_s[t]       = W1s[(size_t)j * HDIM + t];
    w1_s[t + 256] = W1s[(size_t)j * HDIM + t + 256];
    b1_s[t]       = b1s[(size_t)j * HDIM + t];
    b1_s[t + 256] = b1s[(size_t)j * HDIM + t + 256];
    if (t < 64) z_s[t] = encoded[(size_t)(b0 + t) * DDIM + j];
    __syncthreads();

    // ---- per-thread constants ----
    const int m0 = (wid & 1) * 32;              // warp m origin (b)
    const int n0 = (wid >> 1) * 32;             // warp n origin (d)
    const int ar  = ((l >> 3) & 1) * 8 + (l & 7);
    const int ac2 = (l >> 4) * 16;
    const uint32_t swA = (uint32_t)((ar & 7) << 4);
    const int br  = (l >> 4) * 8 + (l & 7);
    const int bc2 = ((l >> 3) & 1) * 16;
    const uint32_t swB = (uint32_t)((br & 7) << 4);
    // A producer: thread -> (b row 0..63, k group of 16)
    const int pb  = t & 63;
    const int pk  = (t >> 6) * 16;              // 0,16,32,48
    const float z = z_s[pb];
    // B producer: thread -> (d rows, 16B segment)
    const int bseg = t & 7;
    const int bd0  = t >> 3;

    float acc[2][4][4] = {};

    auto loadB = [&](int c, int buf) {
        const int hc = c * KC;
#pragma unroll
        for (int p = 0; p < 4; ++p) {
            const int d = p * 32 + bd0;
            const size_t goff = ((size_t)j * DDIM + d) * HDIM + hc + bseg * 8;
            const uint32_t so = sw_off(d, bseg * 16);
            CP_ASYNC16(sbase + S_BHI(buf) + so, w2hi + goff);
            CP_ASYNC16(sbase + S_BLO(buf) + so, w2lo + goff);
        }
    };
    auto storeA = [&](int c, int buf) {
        const int hc = c * KC;
#pragma unroll
        for (int i = 0; i < 2; ++i) {
            const int h = pk + i * 8;
            float v[8], r[8];
#pragma unroll
            for (int q = 0; q < 8; ++q) {
                float u = fmaf(z, w1_s[hc + h + q], b1_s[hc + h + q]);
                u = fmaxf(u, 0.2f * u);
                __nv_bfloat16 hb = __float2bfloat16(u);
                float hf = __bfloat162float(hb);
                v[q] = hf;
                r[q] = u - hf;
            }
            uint4 H, L;
            H.x = pack2(v[0], v[1]); H.y = pack2(v[2], v[3]);
            H.z = pack2(v[4], v[5]); H.w = pack2(v[6], v[7]);
            L.x = pack2(r[0], r[1]); L.y = pack2(r[2], r[3]);
            L.z = pack2(r[4], r[5]); L.w = pack2(r[6], r[7]);
            const uint32_t so = sw_off(pb, h * 2);
            *(uint4*)(smem + S_AHI(buf) + so) = H;
            *(uint4*)(smem + S_ALO(buf) + so) = L;
        }
    };

    auto hmma = [&](int buf) {
        const uint32_t aHi = sbase + S_AHI(buf), aLo = sbase + S_ALO(buf);
        const uint32_t bHi = sbase + S_BHI(buf), bLo = sbase + S_BLO(buf);
#pragma unroll
        for (int ks = 0; ks < KC / 16; ++ks) {
            const int kb = ks * 32;
            uint32_t bh[4][2], bl[4][2];
#pragma unroll
            for (int np = 0; np < 2; ++np) {
                const uint32_t ro = (uint32_t)((n0 + np * 16 + br) * 128);
                const uint32_t co = (uint32_t)(kb + bc2) ^ swB;
                LDSM_X4(bh[np*2][0], bh[np*2][1], bh[np*2+1][0], bh[np*2+1][1],
                        bHi + ro + co);
                LDSM_X4(bl[np*2][0], bl[np*2][1], bl[np*2+1][0], bl[np*2+1][1],
                        bLo + ro + co);
            }
#pragma unroll
            for (int mt = 0; mt < 2; ++mt) {
                const uint32_t ro = (uint32_t)((m0 + mt * 16 + ar) * 128);
                const uint32_t co = (uint32_t)(kb + ac2) ^ swA;
                uint32_t ah[4], al[4];
                LDSM_X4(ah[0], ah[1], ah[2], ah[3], aHi + ro + co);
                LDSM_X4(al[0], al[1], al[2], al[3], aLo + ro + co);
#pragma unroll
                for (int nt = 0; nt < 4; ++nt) {
                    MMA_BF16(acc[mt][nt], ah, bh[nt]);
                    MMA_BF16(acc[mt][nt], ah, bl[nt]);
                    MMA_BF16(acc[mt][nt], al, bh[nt]);
                }
            }
        }
    };

    // ---- pipeline: double A + double B, ONE sync per chunk ----
    loadB(0, 0);
    CP_COMMIT();
    storeA(0, 0);
    CP_WAIT0();
    __syncthreads();

    for (int c = 0; c < HDIM / KC; ++c) {
        const int cb = c & 1;
        if (c < HDIM / KC - 1) {
            loadB(c + 1, cb ^ 1);
            CP_COMMIT();
            storeA(c + 1, cb ^ 1);   // other buffer: no reader conflict
        }
        hmma(cb);
        if (c < HDIM / KC - 1) {
            CP_WAIT0();              // B(c+1) landed (only outstanding group)
            __syncthreads();         // A(c+1)/B(c+1) visible; chunk c reads done
        }
    }

    // ---- epilogue: direct fp32 stores ----
    const int t4 = l >> 2, tn = (l & 3) * 2;
#pragma unroll
    for (int mt = 0; mt < 2; ++mt) {
        const int row0 = b0 + m0 + mt * 16 + t4;
        float* p0 = terms + ((size_t)j * BATCH + row0) * DDIM;
        float* p1 = terms + ((size_t)j * BATCH + row0 + 8) * DDIM;
#pragma unroll
        for (int nt = 0; nt < 4; ++nt) {
            const int col = n0 + nt * 8 + tn;
            *(float2*)&p0[col] = make_float2(acc[mt][nt][0], acc[mt][nt][1]);
            *(float2*)&p1[col] = make_float2(acc[mt][nt][2], acc[mt][nt][3]);
        }
    }
}

// ---------------- kernel 4: cumsum over j + bias + tanh --------------------
__global__ __launch_bounds__(256)
void cumsum_tanh(const float* __restrict__ terms,
                 const float* __restrict__ b2s,
                 float* __restrict__ out)
{
    const int g  = blockIdx.x * 256 + threadIdx.x;
    const int dq = g & 31;
    const size_t jstride = (size_t)BATCH * DDIM / 4;

    const float4* tp = (const float4*)terms + g;
    float4*       op = (float4*)out + g;
    const float4* bp = (const float4*)b2s + dq;

    float4 acc = make_float4(0.f, 0.f, 0.f, 0.f);
#pragma unroll 4
    for (int j = 0; j < DDIM; j++) {
        float4 tv = tp[(size_t)j * jstride];
        float4 bv = bp[(size_t)j * (DDIM / 4)];
        acc.x += tv.x + bv.x;
        acc.y += tv.y + bv.y;
        acc.z += tv.z + bv.z;
        acc.w += tv.w + bv.w;
        float4 o = make_float4(tanhf(acc.x), tanhf(acc.y),
                               tanhf(acc.z), tanhf(acc.w));
        op[(size_t)j * jstride] = o;
    }
}

// ---------------- launch ---------------------------------------------------
extern "C" void kernel_launch(void* const* d_in, const int* in_sizes, int n_in,
                              void* d_out, int out_size)
{
    const float* x   = (const float*)d_in[0];
    const float* We1 = (const float*)d_in[1];
    const float* be1 = (const float*)d_in[2];
    const float* We2 = (const float*)d_in[3];
    const float* be2 = (const float*)d_in[4];
    const float* W1s = (const float*)d_in[5];
    const float* b1s = (const float*)d_in[6];
    const float* W2s = (const float*)d_in[7];
    const float* b2s = (const float*)d_in[8];
    float* out = (float*)d_out;

    float *ench, *enc, *terms;
    __nv_bfloat16 *w2hi, *w2lo;
    cudaGetSymbolAddress((void**)&ench,  g_ench);
    cudaGetSymbolAddress((void**)&enc,   g_enc);
    cudaGetSymbolAddress((void**)&terms, g_terms);
    cudaGetSymbolAddress((void**)&w2hi,  g_w2hi);
    cudaGetSymbolAddress((void**)&w2lo,  g_w2lo);

    cudaFuncSetAttribute(terms_mma_kernel,
                         cudaFuncAttributeMaxDynamicSharedMemorySize, SMEM_TOTAL);

    w2_split_kernel<<<(DDIM * DDIM * HDIM / 4) / 256, 256>>>(
        (const float4*)W2s, (uint2*)w2hi, (uint2*)w2lo);

    gemm_nt_bias_act<<<dim3(BATCH / 64, HDIM / 64), 256>>>(
        x, We1, be1, ench, BATCH, HDIM, DDIM, 0);
    gemm_nt_bias_act<<<dim3(BATCH / 64, DDIM / 64), 256>>>(
        ench, We2, be2, enc, BATCH, DDIM, HDIM, 1);

    terms_mma_kernel<<<dim3(BATCH / 64, DDIM), 256, SMEM_TOTAL>>>(
        enc, W1s, b1s, w2hi, w2lo, terms);

    cumsum_tanh<<<(BATCH * DDIM / 4) / 256, 256>>>(terms, b2s, out);
}

// round 9
// speedup vs baseline: 1.6665x; 1.6439x over previous
#include <cuda_runtime.h>
#include <cuda_fp16.h>
#include <math.h>
#include <stdint.h>

// Shapes (fixed): B=2048, D=128, H=512
#define BATCH 2048
#define DDIM  128
#define HDIM  512

// ---------------- device scratch (static; no allocations) ----------------
__device__ float g_ench [BATCH * HDIM];                  // 4 MB
__device__ float g_enc  [BATCH * DDIM];                  // 1 MB
__device__ float g_terms[DDIM * BATCH * DDIM];           // 134 MB (j,b,d)
__device__ __half g_w2h [DDIM * DDIM * HDIM];            // 16.8 MB (j,d,h) fp16

// ======================= helpers ==========================================
__device__ __forceinline__ uint32_t smem_u32(const void* p) {
    uint32_t a;
    asm("{ .reg .u64 t; cvta.to.shared.u64 t, %1; cvt.u32.u64 %0, t; }"
        : "=r"(a) : "l"(p));
    return a;
}
__device__ __forceinline__ uint32_t pack2h(float a, float b) {
    __half2 t = __floats2half2_rn(a, b);
    return *reinterpret_cast<uint32_t*>(&t);
}
// 128B-row swizzle: XOR byte-col bits[6:4] with (row&7)<<4 (bijective per row)
__device__ __forceinline__ uint32_t sw_off(int row, int colb) {
    return (uint32_t)(row * 128 + (colb ^ ((row & 7) << 4)));
}
#define LDSM_X4(r0, r1, r2, r3, addr)                                          \
    asm volatile("ldmatrix.sync.aligned.m8n8.x4.shared.b16 {%0,%1,%2,%3}, [%4];" \
                 : "=r"(r0), "=r"(r1), "=r"(r2), "=r"(r3) : "r"(addr))
#define MMA_FP16(d, a, b)                                                      \
    asm volatile("mma.sync.aligned.m16n8k16.row.col.f32.f16.f16.f32 "          \
                 "{%0,%1,%2,%3}, {%4,%5,%6,%7}, {%8,%9}, {%0,%1,%2,%3};"       \
                 : "+f"((d)[0]), "+f"((d)[1]), "+f"((d)[2]), "+f"((d)[3])      \
                 : "r"((a)[0]), "r"((a)[1]), "r"((a)[2]), "r"((a)[3]),         \
                   "r"((b)[0]), "r"((b)[1]))
#define CP_ASYNC16(saddr, gptr)                                                \
    asm volatile("cp.async.cg.shared.global [%0], [%1], 16;"                   \
                 :: "r"(saddr), "l"(gptr) : "memory")
#define CP_COMMIT()  asm volatile("cp.async.commit_group;" ::: "memory")
#define CP_WAIT0()   asm volatile("cp.async.wait_group 0;" ::: "memory")

// ---------------- kernel 1: generic NT GEMM + bias + activation ----------
__global__ void gemm_nt_bias_act(const float* __restrict__ A,
                                 const float* __restrict__ Bw,
                                 const float* __restrict__ bias,
                                 float* __restrict__ C,
                                 int M, int N, int K, int act)
{
    __shared__ __align__(16) float As[32][68];
    __shared__ __align__(16) float Bs[32][68];

    const int t  = threadIdx.x;
    const int m0 = blockIdx.x * 64;
    const int n0 = blockIdx.y * 64;
    const int mg = t >> 4;
    const int ng = t & 15;

    float acc[4][4] = {};

    for (int k0 = 0; k0 < K; k0 += 32) {
        __syncthreads();
#pragma unroll
        for (int i = 0; i < 8; i++) {
            int idx = i * 256 + t;
            int m = idx >> 5, k = idx & 31;
            As[k][m] = A [(size_t)(m0 + m) * K + k0 + k];
            Bs[k][m] = Bw[(size_t)(n0 + m) * K + k0 + k];
        }
        __syncthreads();
#pragma unroll
        for (int k = 0; k < 32; k++) {
            float4 av = *(const float4*)&As[k][mg * 4];
            float4 bv = *(const float4*)&Bs[k][ng * 4];
            float a[4] = {av.x, av.y, av.z, av.w};
            float b[4] = {bv.x, bv.y, bv.z, bv.w};
#pragma unroll
            for (int i = 0; i < 4; i++)
#pragma unroll
                for (int jj = 0; jj < 4; jj++)
                    acc[i][jj] = fmaf(a[i], b[jj], acc[i][jj]);
        }
    }

#pragma unroll
    for (int i = 0; i < 4; i++) {
        int m = m0 + mg * 4 + i;
#pragma unroll
        for (int jj = 0; jj < 4; jj++) {
            int n = n0 + ng * 4 + jj;
            float c = acc[i][jj] + bias[n];
            c = (act == 0) ? fmaxf(c, 0.2f * c) : tanhf(c);
            C[(size_t)m * N + n] = c;
        }
    }
}

// ---------------- kernel 2: convert W2s fp32 -> fp16 -----------------------
__global__ void w2_cvt_kernel(const float4* __restrict__ w2,
                              uint2* __restrict__ w2h)
{
    int i = blockIdx.x * blockDim.x + threadIdx.x;
    float4 v = w2[i];
    uint2 H;
    H.x = pack2h(v.x, v.y);
    H.y = pack2h(v.z, v.w);
    w2h[i] = H;
}

// ---------------- kernel 3: terms via mma.sync fp16 ------------------------
// terms[j][b][d] = sum_h leaky(z*w1+b1) * W2[j][d][h]
// CTA tile: M=128 (b) x N=128 (d), K=512 in 8 chunks of 64. Grid 2048.
// 8 warps in 2(m) x 4(n), warp tile 64x32. Double A + double B, 1 sync/chunk.
#define KC 64
#define SM_Z     0
#define SM_W1    512
#define SM_B1    2560
#define SM_TILE0 4608
#define MAT_SZ   16384                    // 128 x 64 fp16
#define S_A(b)   (SM_TILE0 + (b) * MAT_SZ)
#define S_B(b)   (SM_TILE0 + 2 * MAT_SZ + (b) * MAT_SZ)
#define SMEM_TOTAL (SM_TILE0 + 4 * MAT_SZ)   // 70144 B -> 2 CTAs/SM

__global__ __launch_bounds__(256, 2)
void terms_mma_kernel(const float* __restrict__ encoded,
                      const float* __restrict__ W1s,
                      const float* __restrict__ b1s,
                      const __half* __restrict__ w2h,
                      float* __restrict__ terms)
{
    extern __shared__ __align__(128) char smem[];
    const uint32_t sbase = smem_u32(smem);
    const int t   = threadIdx.x;
    const int l   = t & 31;
    const int wid = t >> 5;
    const int j   = blockIdx.y;
    const int b0  = blockIdx.x * 128;

    float* z_s  = (float*)(smem + SM_Z);
    float* w1_s = (float*)(smem + SM_W1);
    float* b1_s = (float*)(smem + SM_B1);

    w1_s[t]       = W1s[(size_t)j * HDIM + t];
    w1_s[t + 256] = W1s[(size_t)j * HDIM + t + 256];
    b1_s[t]       = b1s[(size_t)j * HDIM + t];
    b1_s[t + 256] = b1s[(size_t)j * HDIM + t + 256];
    if (t < 128) z_s[t] = encoded[(size_t)(b0 + t) * DDIM + j];
    __syncthreads();

    // ---- per-thread constants ----
    const int m0 = (wid & 1) * 64;              // warp m origin (b)
    const int n0 = (wid >> 1) * 32;             // warp n origin (d)
    const int ar  = ((l >> 3) & 1) * 8 + (l & 7);
    const int ac2 = (l >> 4) * 16;
    const uint32_t swA = (uint32_t)((ar & 7) << 4);
    const int br  = (l >> 4) * 8 + (l & 7);
    const int bc2 = ((l >> 3) & 1) * 16;
    const uint32_t swB = (uint32_t)((br & 7) << 4);
    // A producer: thread -> (b row 0..127, 32 h values)
    const int pb  = t & 127;
    const int pk  = (t >> 7) * 32;              // 0 or 32
    const float z = z_s[pb];
    // B producer: thread -> (d rows, 16B segment)
    const int bseg = t & 7;
    const int bd0  = t >> 3;

    float acc[4][4][4] = {};

    auto loadB = [&](int c, int buf) {
        const int hc = c * KC;
#pragma unroll
        for (int p = 0; p < 4; ++p) {
            const int d = p * 32 + bd0;
            const size_t goff = ((size_t)j * DDIM + d) * HDIM + hc + bseg * 8;
            CP_ASYNC16(sbase + S_B(buf) + sw_off(d, bseg * 16), w2h + goff);
        }
    };
    auto storeA = [&](int c, int buf) {
        const int hc = c * KC;
#pragma unroll
        for (int i = 0; i < 4; ++i) {
            const int h = pk + i * 8;
            float v[8];
#pragma unroll
            for (int q = 0; q < 8; ++q) {
                float u = fmaf(z, w1_s[hc + h + q], b1_s[hc + h + q]);
                v[q] = fmaxf(u, 0.2f * u);
            }
            uint4 H;
            H.x = pack2h(v[0], v[1]); H.y = pack2h(v[2], v[3]);
            H.z = pack2h(v[4], v[5]); H.w = pack2h(v[6], v[7]);
            *(uint4*)(smem + S_A(buf) + sw_off(pb, h * 2)) = H;
        }
    };

    auto hmma = [&](int buf) {
        const uint32_t aB = sbase + S_A(buf);
        const uint32_t bB = sbase + S_B(buf);
#pragma unroll
        for (int ks = 0; ks < KC / 16; ++ks) {
            const int kb = ks * 32;
            uint32_t bf[4][2];
#pragma unroll
            for (int np = 0; np < 2; ++np) {
                const uint32_t ro = (uint32_t)((n0 + np * 16 + br) * 128);
                const uint32_t co = (uint32_t)(kb + bc2) ^ swB;
                LDSM_X4(bf[np*2][0], bf[np*2][1], bf[np*2+1][0], bf[np*2+1][1],
                        bB + ro + co);
            }
#pragma unroll
            for (int mt = 0; mt < 4; ++mt) {
                const uint32_t ro = (uint32_t)((m0 + mt * 16 + ar) * 128);
                const uint32_t co = (uint32_t)(kb + ac2) ^ swA;
                uint32_t af[4];
                LDSM_X4(af[0], af[1], af[2], af[3], aB + ro + co);
#pragma unroll
                for (int nt = 0; nt < 4; ++nt)
                    MMA_FP16(acc[mt][nt], af, bf[nt]);
            }
        }
    };

    // ---- pipeline: double A + double B, one sync per chunk ----
    loadB(0, 0);
    CP_COMMIT();
    storeA(0, 0);
    CP_WAIT0();
    __syncthreads();

    for (int c = 0; c < HDIM / KC; ++c) {
        const int cb = c & 1;
        if (c < HDIM / KC - 1) {
            loadB(c + 1, cb ^ 1);
            CP_COMMIT();
            storeA(c + 1, cb ^ 1);   // other buffer: no reader conflict
        }
        hmma(cb);
        if (c < HDIM / KC - 1) {
            CP_WAIT0();
            __syncthreads();
        }
    }

    // ---- epilogue: direct fp32 stores ----
    const int t4 = l >> 2, tn = (l & 3) * 2;
#pragma unroll
    for (int mt = 0; mt < 4; ++mt) {
        const int row0 = b0 + m0 + mt * 16 + t4;
        float* p0 = terms + ((size_t)j * BATCH + row0) * DDIM;
        float* p1 = terms + ((size_t)j * BATCH + row0 + 8) * DDIM;
#pragma unroll
        for (int nt = 0; nt < 4; ++nt) {
            const int col = n0 + nt * 8 + tn;
            *(float2*)&p0[col] = make_float2(acc[mt][nt][0], acc[mt][nt][1]);
            *(float2*)&p1[col] = make_float2(acc[mt][nt][2], acc[mt][nt][3]);
        }
    }
}

// ---------------- kernel 4: cumsum over j + bias + tanh --------------------
__global__ __launch_bounds__(256)
void cumsum_tanh(const float* __restrict__ terms,
                 const float* __restrict__ b2s,
                 float* __restrict__ out)
{
    const int g  = blockIdx.x * 256 + threadIdx.x;
    const int dq = g & 31;
    const size_t jstride = (size_t)BATCH * DDIM / 4;

    const float4* tp = (const float4*)terms + g;
    float4*       op = (float4*)out + g;
    const float4* bp = (const float4*)b2s + dq;

    float4 acc = make_float4(0.f, 0.f, 0.f, 0.f);
#pragma unroll 4
    for (int j = 0; j < DDIM; j++) {
        float4 tv = tp[(size_t)j * jstride];
        float4 bv = bp[(size_t)j * (DDIM / 4)];
        acc.x += tv.x + bv.x;
        acc.y += tv.y + bv.y;
        acc.z += tv.z + bv.z;
        acc.w += tv.w + bv.w;
        float4 o = make_float4(tanhf(acc.x), tanhf(acc.y),
                               tanhf(acc.z), tanhf(acc.w));
        op[(size_t)j * jstride] = o;
    }
}

// ---------------- launch ---------------------------------------------------
extern "C" void kernel_launch(void* const* d_in, const int* in_sizes, int n_in,
                              void* d_out, int out_size)
{
    const float* x   = (const float*)d_in[0];
    const float* We1 = (const float*)d_in[1];
    const float* be1 = (const float*)d_in[2];
    const float* We2 = (const float*)d_in[3];
    const float* be2 = (const float*)d_in[4];
    const float* W1s = (const float*)d_in[5];
    const float* b1s = (const float*)d_in[6];
    const float* W2s = (const float*)d_in[7];
    const float* b2s = (const float*)d_in[8];
    float* out = (float*)d_out;

    float *ench, *enc, *terms;
    __half *w2h;
    cudaGetSymbolAddress((void**)&ench,  g_ench);
    cudaGetSymbolAddress((void**)&enc,   g_enc);
    cudaGetSymbolAddress((void**)&terms, g_terms);
    cudaGetSymbolAddress((void**)&w2h,   g_w2h);

    cudaFuncSetAttribute(terms_mma_kernel,
                         cudaFuncAttributeMaxDynamicSharedMemorySize, SMEM_TOTAL);

    w2_cvt_kernel<<<(DDIM * DDIM * HDIM / 4) / 256, 256>>>(
        (const float4*)W2s, (uint2*)w2h);

    gemm_nt_bias_act<<<dim3(BATCH / 64, HDIM / 64), 256>>>(
        x, We1, be1, ench, BATCH, HDIM, DDIM, 0);
    gemm_nt_bias_act<<<dim3(BATCH / 64, DDIM / 64), 256>>>(
        ench, We2, be2, enc, BATCH, DDIM, HDIM, 1);

    terms_mma_kernel<<<dim3(BATCH / 128, DDIM), 256, SMEM_TOTAL>>>(
        enc, W1s, b1s, w2h, terms);

    cumsum_tanh<<<(BATCH * DDIM / 4) / 256, 256>>>(terms, b2s, out);
}